// round 1
// baseline (speedup 1.0000x reference)
#include <cuda_runtime.h>
#include <cstdint>

#define N_SRC  200000
#define N_DSTN 100000
#define N_EDGE 500000
#define DFEAT  128

// ---------------------------------------------------------------------------
// Kernel 1: edge scatter-add.  One warp per edge.  Each lane moves one float4
// (16B) of the 512B feature row: coalesced gather from x[src], vectorized
// red.global.add.v4.f32 into out[dst] (out doubles as the agg buffer).
// ---------------------------------------------------------------------------
__global__ __launch_bounds__(256)
void sage_scatter_kernel(const float* __restrict__ x,
                         const int* __restrict__ src,
                         const int* __restrict__ dst,
                         float* __restrict__ agg) {
    int w    = (blockIdx.x * blockDim.x + threadIdx.x) >> 5;   // edge id
    int lane = threadIdx.x & 31;
    if (w >= N_EDGE) return;
    int s = __ldg(src + w);
    int d = __ldg(dst + w);
    float4 v = *(((const float4*)(x + (size_t)s * DFEAT)) + lane);
    float* o = agg + (size_t)d * DFEAT + (lane << 2);
    asm volatile("red.global.add.v4.f32 [%0], {%1,%2,%3,%4};"
                 :: "l"(o), "f"(v.x), "f"(v.y), "f"(v.z), "f"(v.w)
                 : "memory");
}

// ---------------------------------------------------------------------------
// Kernel 2: fused dual GEMM.
//   out[i, :] = (agg[i,:]/deg[i]) @ W1^T + x[self[i],:] @ W2^T
// Virtual K=256 GEMM: A_virt = [agg/deg | x_self], B_cat[k][j] = W{1,2}[j][k].
// agg is read from d_out and overwritten in place (row-local dependency only).
// TILE_M=128 rows/block, 256 threads, 8x8 micro-tile per thread.
// Smem: Bs[256][128] (k-major weights), As[128][132] (row-major A chunk).
// ---------------------------------------------------------------------------
#define TILE_M    128
#define KC        128
#define AS_STRIDE 132                           // 128 + 4 pad (16B aligned rows)
#define GEMM_THREADS 256
#define BS_ELEMS  (256 * DFEAT)                 // 32768 floats
#define AS_ELEMS  (TILE_M * AS_STRIDE)          // 16896 floats
#define SMEM_FLOATS (BS_ELEMS + AS_ELEMS + TILE_M + TILE_M)
#define SMEM_BYTES  (SMEM_FLOATS * 4)           // 199,680 B

__global__ __launch_bounds__(GEMM_THREADS, 1)
void sage_gemm_kernel(const float* __restrict__ x,
                      const float* __restrict__ W1,
                      const float* __restrict__ W2,
                      const float* __restrict__ degree,
                      const int* __restrict__ self_ids,
                      float* __restrict__ out) {
    extern __shared__ float smem[];
    float* Bs   = smem;                       // [256][128]
    float* As   = Bs + BS_ELEMS;              // [128][132]
    float* sinv = As + AS_ELEMS;              // [128]
    int*   sself = (int*)(sinv + TILE_M);     // [128]

    const int tid  = threadIdx.x;
    const int row0 = blockIdx.x * TILE_M;

    // per-row metadata (clamped for the ragged last block)
    if (tid < TILE_M) {
        int r  = row0 + tid;
        int rc = (r < N_DSTN) ? r : (N_DSTN - 1);
        sinv[tid]  = 1.0f / degree[rc];
        sself[tid] = self_ids[rc];
    }

    // Load Bs = [W1 ; W2] transposed to k-major: Bs[k][j] = W[j][k].
    // Lanes take consecutive j -> STS conflict-free; global reads are
    // scattered 16B but W1/W2 are only 128KB total and L1/L2 resident.
    #pragma unroll
    for (int it = 0; it < 32; ++it) {
        int idx = it * GEMM_THREADS + tid;        // 0..8191
        int j   = idx & 127;
        int k4  = (idx >> 7) & 31;
        const float* W = (idx < 4096) ? W1 : W2;
        float4 wv = *((const float4*)(W + j * DFEAT) + k4);
        int kb = ((idx >> 12) << 7) + (k4 << 2);  // mat*128 + k4*4
        Bs[(kb + 0) * DFEAT + j] = wv.x;
        Bs[(kb + 1) * DFEAT + j] = wv.y;
        Bs[(kb + 2) * DFEAT + j] = wv.z;
        Bs[(kb + 3) * DFEAT + j] = wv.w;
    }

    const int tx = tid & 15;          // column group: j0 = tx*8
    const int ty = tid >> 4;          // row group:    i0 = ty*8
    const int i0 = ty * 8;
    const int j0 = tx * 8;

    float acc[8][8];
    #pragma unroll
    for (int ii = 0; ii < 8; ++ii)
        #pragma unroll
        for (int jj = 0; jj < 8; ++jj)
            acc[ii][jj] = 0.0f;

    __syncthreads();   // Bs, sinv, sself ready

    #pragma unroll
    for (int chunk = 0; chunk < 2; ++chunk) {
        // Load A chunk (128 rows x 128 k) as straight float4 copies.
        // chunk 0: agg rows from d_out, scaled by 1/deg; chunk 1: x[self].
        #pragma unroll
        for (int it = 0; it < 16; ++it) {
            int idx = it * GEMM_THREADS + tid;    // 0..4095
            int k4  = idx & 31;
            int i   = idx >> 5;
            float4 v;
            if (chunk == 0) {
                int r  = row0 + i;
                int rc = (r < N_DSTN) ? r : (N_DSTN - 1);
                v = *((const float4*)(out + (size_t)rc * DFEAT) + k4);
                float s = sinv[i];
                v.x *= s; v.y *= s; v.z *= s; v.w *= s;
            } else {
                v = *((const float4*)(x + (size_t)sself[i] * DFEAT) + k4);
            }
            *((float4*)(As + i * AS_STRIDE) + k4) = v;
        }
        __syncthreads();

        const float* Bc = Bs + chunk * KC * DFEAT;
        #pragma unroll 2
        for (int kk = 0; kk < KC; ++kk) {
            float a[8];
            #pragma unroll
            for (int ii = 0; ii < 8; ++ii)
                a[ii] = As[(i0 + ii) * AS_STRIDE + kk];
            float4 b0 = *(const float4*)(Bc + kk * DFEAT + j0);
            float4 b1 = *(const float4*)(Bc + kk * DFEAT + j0 + 4);
            float b[8] = {b0.x, b0.y, b0.z, b0.w, b1.x, b1.y, b1.z, b1.w};
            #pragma unroll
            for (int ii = 0; ii < 8; ++ii)
                #pragma unroll
                for (int jj = 0; jj < 8; ++jj)
                    acc[ii][jj] = fmaf(a[ii], b[jj], acc[ii][jj]);
        }
        __syncthreads();
    }

    // Epilogue: overwrite out rows (all reads of these rows are done).
    #pragma unroll
    for (int ii = 0; ii < 8; ++ii) {
        int r = row0 + i0 + ii;
        if (r < N_DSTN) {
            float4 o0 = make_float4(acc[ii][0], acc[ii][1], acc[ii][2], acc[ii][3]);
            float4 o1 = make_float4(acc[ii][4], acc[ii][5], acc[ii][6], acc[ii][7]);
            float* op = out + (size_t)r * DFEAT + j0;
            *(float4*)(op)     = o0;
            *(float4*)(op + 4) = o1;
        }
    }
}

// ---------------------------------------------------------------------------
// Launch: memset(out) -> scatter -> fused GEMM (in-place over out).
// All stream-ordered, graph-capturable, allocation-free.
// ---------------------------------------------------------------------------
extern "C" void kernel_launch(void* const* d_in, const int* in_sizes, int n_in,
                              void* d_out, int out_size) {
    const float* x        = (const float*)d_in[0];
    const float* W1       = (const float*)d_in[1];
    const float* W2       = (const float*)d_in[2];
    const float* degree   = (const float*)d_in[3];
    const int*   src_idx  = (const int*)d_in[4];
    const int*   dst_idx  = (const int*)d_in[5];
    const int*   self_ids = (const int*)d_in[6];
    float*       out      = (float*)d_out;

    (void)in_sizes; (void)n_in; (void)out_size;

    cudaMemsetAsync(out, 0, (size_t)N_DSTN * DFEAT * sizeof(float));

    // 8 warps/block, one edge per warp
    sage_scatter_kernel<<<N_EDGE / 8, 256>>>(x, src_idx, dst_idx, out);

    cudaFuncSetAttribute(sage_gemm_kernel,
                         cudaFuncAttributeMaxDynamicSharedMemorySize,
                         SMEM_BYTES);
    int gemm_blocks = (N_DSTN + TILE_M - 1) / TILE_M;   // 782
    sage_gemm_kernel<<<gemm_blocks, GEMM_THREADS, SMEM_BYTES>>>(
        x, W1, W2, degree, self_ids, out);
}

// round 6
// speedup vs baseline: 1.7862x; 1.7862x over previous
#include <cuda_runtime.h>
#include <cuda_bf16.h>
#include <cstdint>

#define N_SRC  200000
#define N_DSTN 100000
#define N_EDGE 500000
#define DFEAT  128

// ===========================================================================
// Common helpers
// ===========================================================================
__device__ __forceinline__ uint32_t smem_to_u32(const void* p) {
    uint32_t a;
    asm("{ .reg .u64 t; cvta.to.shared.u64 t, %1; cvt.u32.u64 %0, t; }"
        : "=r"(a) : "l"(p));
    return a;
}

// ldmatrix x4 (A frags: 16x16 bf16 tile -> 4 regs/thread)
__device__ __forceinline__ void ldmatrix_x4(uint32_t* r, uint32_t addr) {
    asm volatile("ldmatrix.sync.aligned.m8n8.x4.shared.b16 {%0,%1,%2,%3}, [%4];"
                 : "=r"(r[0]), "=r"(r[1]), "=r"(r[2]), "=r"(r[3]) : "r"(addr));
}
// ldmatrix x2 (B frags: 16x8 bf16 tile -> 2 regs/thread)
__device__ __forceinline__ void ldmatrix_x2(uint32_t* r, uint32_t addr) {
    asm volatile("ldmatrix.sync.aligned.m8n8.x2.shared.b16 {%0,%1}, [%2];"
                 : "=r"(r[0]), "=r"(r[1]) : "r"(addr));
}
// D += A*B  (m16n8k16, bf16 in, fp32 accum)
__device__ __forceinline__ void mma_16816(float* c, const uint32_t* a, const uint32_t* b) {
    asm volatile("mma.sync.aligned.m16n8k16.row.col.f32.bf16.bf16.f32 "
                 "{%0,%1,%2,%3}, {%4,%5,%6,%7}, {%8,%9}, {%0,%1,%2,%3};"
                 : "+f"(c[0]), "+f"(c[1]), "+f"(c[2]), "+f"(c[3])
                 : "r"(a[0]), "r"(a[1]), "r"(a[2]), "r"(a[3]),
                   "r"(b[0]), "r"(b[1]));
}

// split fp32x4 -> (bf16 hi x4, bf16 lo x4); store 8B to each buffer
__device__ __forceinline__ void split_store4(char* hi_base, char* lo_base,
                                             uint32_t off, float4 v) {
    float f[4] = {v.x, v.y, v.z, v.w};
    __nv_bfloat16 h[4], l[4];
#pragma unroll
    for (int t = 0; t < 4; ++t) {
        h[t] = __float2bfloat16(f[t]);
        l[t] = __float2bfloat16(f[t] - __bfloat162float(h[t]));
    }
    uint32_t h01, h23, l01, l23;
    asm("mov.b32 %0, {%1, %2};" : "=r"(h01) : "h"(*(uint16_t*)&h[0]), "h"(*(uint16_t*)&h[1]));
    asm("mov.b32 %0, {%1, %2};" : "=r"(h23) : "h"(*(uint16_t*)&h[2]), "h"(*(uint16_t*)&h[3]));
    asm("mov.b32 %0, {%1, %2};" : "=r"(l01) : "h"(*(uint16_t*)&l[0]), "h"(*(uint16_t*)&l[1]));
    asm("mov.b32 %0, {%1, %2};" : "=r"(l23) : "h"(*(uint16_t*)&l[2]), "h"(*(uint16_t*)&l[3]));
    *(uint2*)(hi_base + off) = make_uint2(h01, h23);
    *(uint2*)(lo_base + off) = make_uint2(l01, l23);
}

// Pre-split weight tiles, plain row-major [j][k] bf16 128x128.
// [0]=W1 hi, [1]=W1 lo, [2]=W2 hi, [3]=W2 lo
#define WTILE_BYTES (128 * 128 * 2)
__device__ __align__(16) unsigned char g_wtiles[4][WTILE_BYTES];

// ===========================================================================
// Kernel 0: split W1/W2 into bf16 hi/lo tiles (once, 2 blocks).
// ===========================================================================
__global__ __launch_bounds__(256)
void prep_weights_kernel(const float* __restrict__ W1,
                         const float* __restrict__ W2) {
    const float* W = blockIdx.x ? W2 : W1;
    char* hi = (char*)g_wtiles[blockIdx.x * 2 + 0];
    char* lo = (char*)g_wtiles[blockIdx.x * 2 + 1];
#pragma unroll
    for (int it = 0; it < 16; ++it) {
        int idx = it * 256 + threadIdx.x;   // 0..4095
        int k4  = idx & 31;
        int j   = idx >> 5;
        float4 v = *((const float4*)(W + (size_t)j * DFEAT) + k4);
        split_store4(hi, lo, (uint32_t)(j * DFEAT + k4 * 4) * 2, v);
    }
}

// ===========================================================================
// Kernel 1: edge scatter-add. One warp per edge; vectorized red.global.
// ===========================================================================
__global__ __launch_bounds__(256)
void sage_scatter_kernel(const float* __restrict__ x,
                         const int* __restrict__ src,
                         const int* __restrict__ dst,
                         float* __restrict__ agg) {
    int w    = (blockIdx.x * blockDim.x + threadIdx.x) >> 5;
    int lane = threadIdx.x & 31;
    if (w >= N_EDGE) return;
    int s = __ldg(src + w);
    int d = __ldg(dst + w);
    float4 v = *(((const float4*)(x + (size_t)s * DFEAT)) + lane);
    float* o = agg + (size_t)d * DFEAT + (lane << 2);
    asm volatile("red.global.add.v4.f32 [%0], {%1,%2,%3,%4};"
                 :: "l"(o), "f"(v.x), "f"(v.y), "f"(v.z), "f"(v.w)
                 : "memory");
}

// ===========================================================================
// Kernel 2: mma.sync bf16-split dual GEMM.
//   out[i,:] = (agg[i,:]/deg[i]) @ W1^T + x[self[i],:] @ W2^T
// Virtual K=256 (chunk0: agg/W1, chunk1: x[self]/W2), bf16 hi/lo split,
// D += Ah·Bh + Ah·Bl + Al·Bh with fp32 register accumulators.
// Block: 128x128 out, 256 threads (8 warps in 2x4), warp tile 64x32,
// per-warp frags: 4 m-frags (m16) x 4 n-frags (n8), k-steps of 16.
// agg is read from d_out and overwritten in place (row-local dependency).
// ===========================================================================
#define TILE_M    128
#define ASTRIDE   136      // bf16 elems per smem row (128 + 8 pad); 272B rows
#define TILE_SM_BYTES (128 * ASTRIDE * 2)    // 34816
#define SMEM_SINV 0                          // float[128]
#define SMEM_SELF 512                        // int[128]
#define SMEM_AHI  1024
#define SMEM_ALO  (SMEM_AHI + TILE_SM_BYTES)  // 35840
#define SMEM_BHI  (SMEM_ALO + TILE_SM_BYTES)  // 70656
#define SMEM_BLO  (SMEM_BHI + TILE_SM_BYTES)  // 105472
#define SMEM_BYTES (SMEM_BLO + TILE_SM_BYTES + 128)  // 140,416 B

#define GEMM_THREADS 256

__global__ __launch_bounds__(GEMM_THREADS, 1)
void sage_mma_gemm_kernel(const float* __restrict__ x,
                          const float* __restrict__ degree,
                          const int* __restrict__ self_ids,
                          float* __restrict__ out) {
    extern __shared__ char smem[];
    uint32_t sb = smem_to_u32(smem);
    const int tid  = threadIdx.x;
    const int wid  = tid >> 5;
    const int lane = tid & 31;
    const int row0 = blockIdx.x * TILE_M;

    const int warp_m = wid & 1;    // 0..1 -> 64-row block
    const int warp_n = wid >> 1;   // 0..3 -> 32-col block

    float* sinv  = (float*)(smem + SMEM_SINV);
    int*   sself = (int*)(smem + SMEM_SELF);

    if (tid < TILE_M) {
        int r  = row0 + tid;
        int rc = (r < N_DSTN) ? r : (N_DSTN - 1);
        sinv[tid]  = 1.0f / degree[rc];
        sself[tid] = self_ids[rc];
    }

    // accumulators: [m-frag][n-frag][4]
    float acc[4][4][4];
#pragma unroll
    for (int mf = 0; mf < 4; ++mf)
#pragma unroll
        for (int nf = 0; nf < 4; ++nf)
#pragma unroll
            for (int q = 0; q < 4; ++q) acc[mf][nf][q] = 0.0f;

    __syncthreads();   // sinv/sself visible

    // precomputed ldmatrix lane address components
    const int a_row  = warp_m * 64 + (lane & 15);       // + mf*16
    const int a_koff = (lane >> 4) * 8;                 // + k0
    const int b_row  = warp_n * 32 + (lane & 7);        // + nf*8
    const int b_koff = ((lane >> 3) & 1) * 8;           // + k0

#pragma unroll
    for (int chunk = 0; chunk < 2; ++chunk) {
        // ---- A tile: gather fp32, scale, split into padded row-major bf16 ----
#pragma unroll
        for (int it = 0; it < 16; ++it) {
            int idx = it * GEMM_THREADS + tid;     // 0..4095
            int k4  = idx & 31;
            int i   = idx >> 5;
            float4 v;
            if (chunk == 0) {
                int r  = row0 + i;
                int rc = (r < N_DSTN) ? r : (N_DSTN - 1);
                v = *((const float4*)(out + (size_t)rc * DFEAT) + k4);
                float s = sinv[i];
                v.x *= s; v.y *= s; v.z *= s; v.w *= s;
            } else {
                v = *((const float4*)(x + (size_t)sself[i] * DFEAT) + k4);
            }
            uint32_t off = (uint32_t)(i * ASTRIDE + k4 * 4) * 2;
            split_store4(smem + SMEM_AHI, smem + SMEM_ALO, off, v);
        }
        // ---- B tiles: copy pre-split weights into padded smem rows ----
        {
            const uint4* ghi = (const uint4*)g_wtiles[chunk * 2 + 0];
            const uint4* glo = (const uint4*)g_wtiles[chunk * 2 + 1];
#pragma unroll
            for (int it = 0; it < 8; ++it) {
                int idx = it * GEMM_THREADS + tid;   // 0..2047
                int j   = idx >> 4;                  // row (16 x 16B per row)
                int kq  = idx & 15;
                uint32_t off = (uint32_t)(j * ASTRIDE) * 2 + (uint32_t)kq * 16;
                *(uint4*)(smem + SMEM_BHI + off) = __ldg(ghi + idx);
                *(uint4*)(smem + SMEM_BLO + off) = __ldg(glo + idx);
            }
        }
        __syncthreads();

        // ---- compute: 8 k-steps of 16; 3 products per (mf, nf) ----
#pragma unroll
        for (int ks = 0; ks < 8; ++ks) {
            const int k0 = ks * 16;
            uint32_t ah[4][4], al[4][4], bh[4][2], bl[4][2];
#pragma unroll
            for (int mf = 0; mf < 4; ++mf) {
                uint32_t boff = (uint32_t)((a_row + mf * 16) * ASTRIDE + k0 + a_koff) * 2;
                ldmatrix_x4(ah[mf], sb + SMEM_AHI + boff);
                ldmatrix_x4(al[mf], sb + SMEM_ALO + boff);
            }
#pragma unroll
            for (int nf = 0; nf < 4; ++nf) {
                uint32_t boff = (uint32_t)((b_row + nf * 8) * ASTRIDE + k0 + b_koff) * 2;
                ldmatrix_x2(bh[nf], sb + SMEM_BHI + boff);
                ldmatrix_x2(bl[nf], sb + SMEM_BLO + boff);
            }
#pragma unroll
            for (int mf = 0; mf < 4; ++mf)
#pragma unroll
                for (int nf = 0; nf < 4; ++nf) {
                    mma_16816(acc[mf][nf], ah[mf], bh[nf]);
                    mma_16816(acc[mf][nf], ah[mf], bl[nf]);
                    mma_16816(acc[mf][nf], al[mf], bh[nf]);
                }
        }
        __syncthreads();   // done reading smem before next chunk overwrites
    }

    // ---- epilogue: direct stores (float2 per frag row; 32B per quad) ----
#pragma unroll
    for (int mf = 0; mf < 4; ++mf) {
#pragma unroll
        for (int nf = 0; nf < 4; ++nf) {
            int r0 = row0 + warp_m * 64 + mf * 16 + (lane >> 2);
            int r1 = r0 + 8;
            int col = warp_n * 32 + nf * 8 + (lane & 3) * 2;
            if (r0 < N_DSTN)
                *(float2*)(out + (size_t)r0 * DFEAT + col) =
                    make_float2(acc[mf][nf][0], acc[mf][nf][1]);
            if (r1 < N_DSTN)
                *(float2*)(out + (size_t)r1 * DFEAT + col) =
                    make_float2(acc[mf][nf][2], acc[mf][nf][3]);
        }
    }
}

// ===========================================================================
// Launch: prep_weights + memset(out) -> scatter -> mma GEMM (in place).
// All stream-ordered, graph-capturable, allocation-free.
// ===========================================================================
extern "C" void kernel_launch(void* const* d_in, const int* in_sizes, int n_in,
                              void* d_out, int out_size) {
    const float* x        = (const float*)d_in[0];
    const float* W1       = (const float*)d_in[1];
    const float* W2       = (const float*)d_in[2];
    const float* degree   = (const float*)d_in[3];
    const int*   src_idx  = (const int*)d_in[4];
    const int*   dst_idx  = (const int*)d_in[5];
    const int*   self_ids = (const int*)d_in[6];
    float*       out      = (float*)d_out;

    (void)in_sizes; (void)n_in; (void)out_size;

    prep_weights_kernel<<<2, 256>>>(W1, W2);
    cudaMemsetAsync(out, 0, (size_t)N_DSTN * DFEAT * sizeof(float));

    sage_scatter_kernel<<<N_EDGE / 8, 256>>>(x, src_idx, dst_idx, out);

    cudaFuncSetAttribute(sage_mma_gemm_kernel,
                         cudaFuncAttributeMaxDynamicSharedMemorySize, SMEM_BYTES);
    int gemm_blocks = (N_DSTN + TILE_M - 1) / TILE_M;   // 782
    sage_mma_gemm_kernel<<<gemm_blocks, GEMM_THREADS, SMEM_BYTES>>>(
        x, degree, self_ids, out);
}

// round 7
// speedup vs baseline: 2.1065x; 1.1793x over previous
#include <cuda_runtime.h>
#include <cuda_bf16.h>
#include <cstdint>

#define N_SRC  200000
#define N_DSTN 100000
#define N_EDGE 500000
#define DFEAT  128

// ===========================================================================
// Common helpers
// ===========================================================================
__device__ __forceinline__ uint32_t smem_to_u32(const void* p) {
    uint32_t a;
    asm("{ .reg .u64 t; cvta.to.shared.u64 t, %1; cvt.u32.u64 %0, t; }"
        : "=r"(a) : "l"(p));
    return a;
}

// ldmatrix x4 (A frags: 16x16 bf16 tile -> 4 regs/thread)
__device__ __forceinline__ void ldmatrix_x4(uint32_t* r, uint32_t addr) {
    asm volatile("ldmatrix.sync.aligned.m8n8.x4.shared.b16 {%0,%1,%2,%3}, [%4];"
                 : "=r"(r[0]), "=r"(r[1]), "=r"(r[2]), "=r"(r[3]) : "r"(addr));
}
// ldmatrix x2 (B frags: 16x8 bf16 tile -> 2 regs/thread)
__device__ __forceinline__ void ldmatrix_x2(uint32_t* r, uint32_t addr) {
    asm volatile("ldmatrix.sync.aligned.m8n8.x2.shared.b16 {%0,%1}, [%2];"
                 : "=r"(r[0]), "=r"(r[1]) : "r"(addr));
}
// D += A*B  (m16n8k16, bf16 in, fp32 accum)
__device__ __forceinline__ void mma_16816(float* c, const uint32_t* a, const uint32_t* b) {
    asm volatile("mma.sync.aligned.m16n8k16.row.col.f32.bf16.bf16.f32 "
                 "{%0,%1,%2,%3}, {%4,%5,%6,%7}, {%8,%9}, {%0,%1,%2,%3};"
                 : "+f"(c[0]), "+f"(c[1]), "+f"(c[2]), "+f"(c[3])
                 : "r"(a[0]), "r"(a[1]), "r"(a[2]), "r"(a[3]),
                   "r"(b[0]), "r"(b[1]));
}

// split fp32x4 -> (bf16 hi x4, bf16 lo x4); store 8B to each buffer
__device__ __forceinline__ void split_store4(char* hi_base, char* lo_base,
                                             uint32_t off, float4 v) {
    float f[4] = {v.x, v.y, v.z, v.w};
    __nv_bfloat16 h[4], l[4];
#pragma unroll
    for (int t = 0; t < 4; ++t) {
        h[t] = __float2bfloat16(f[t]);
        l[t] = __float2bfloat16(f[t] - __bfloat162float(h[t]));
    }
    uint32_t h01, h23, l01, l23;
    asm("mov.b32 %0, {%1, %2};" : "=r"(h01) : "h"(*(uint16_t*)&h[0]), "h"(*(uint16_t*)&h[1]));
    asm("mov.b32 %0, {%1, %2};" : "=r"(h23) : "h"(*(uint16_t*)&h[2]), "h"(*(uint16_t*)&h[3]));
    asm("mov.b32 %0, {%1, %2};" : "=r"(l01) : "h"(*(uint16_t*)&l[0]), "h"(*(uint16_t*)&l[1]));
    asm("mov.b32 %0, {%1, %2};" : "=r"(l23) : "h"(*(uint16_t*)&l[2]), "h"(*(uint16_t*)&l[3]));
    *(uint2*)(hi_base + off) = make_uint2(h01, h23);
    *(uint2*)(lo_base + off) = make_uint2(l01, l23);
}

// Pre-split weight tiles, plain row-major [j][k] bf16 128x128.
// [0]=W1 hi, [1]=W1 lo, [2]=W2 hi, [3]=W2 lo
#define WTILE_BYTES (128 * 128 * 2)
__device__ __align__(16) unsigned char g_wtiles[4][WTILE_BYTES];

// ===========================================================================
// Kernel 0: split W1/W2 into bf16 hi/lo tiles.
// grid = 32 blocks (16 per matrix), 256 threads, 1 float4 per thread.
// ===========================================================================
__global__ __launch_bounds__(256)
void prep_weights_kernel(const float* __restrict__ W1,
                         const float* __restrict__ W2) {
    int mat  = blockIdx.x >> 4;           // 0: W1, 1: W2
    int part = blockIdx.x & 15;
    const float* W = mat ? W2 : W1;
    char* hi = (char*)g_wtiles[mat * 2 + 0];
    char* lo = (char*)g_wtiles[mat * 2 + 1];
    int idx = part * 256 + threadIdx.x;   // 0..4095
    int k4  = idx & 31;
    int j   = idx >> 5;
    float4 v = *((const float4*)(W + (size_t)j * DFEAT) + k4);
    split_store4(hi, lo, (uint32_t)(j * DFEAT + k4 * 4) * 2, v);
}

// ===========================================================================
// Kernel 1: edge scatter-add. One warp per edge; vectorized red.global.
// ===========================================================================
__global__ __launch_bounds__(256)
void sage_scatter_kernel(const float* __restrict__ x,
                         const int* __restrict__ src,
                         const int* __restrict__ dst,
                         float* __restrict__ agg) {
    int w    = (blockIdx.x * blockDim.x + threadIdx.x) >> 5;
    int lane = threadIdx.x & 31;
    if (w >= N_EDGE) return;
    int s = __ldg(src + w);
    int d = __ldg(dst + w);
    float4 v = *(((const float4*)(x + (size_t)s * DFEAT)) + lane);
    float* o = agg + (size_t)d * DFEAT + (lane << 2);
    asm volatile("red.global.add.v4.f32 [%0], {%1,%2,%3,%4};"
                 :: "l"(o), "f"(v.x), "f"(v.y), "f"(v.z), "f"(v.w)
                 : "memory");
}

// ===========================================================================
// Kernel 2: mma.sync bf16-split dual GEMM, TILE_M=64, 2 CTAs/SM.
//   out[i,:] = (agg[i,:]/deg[i]) @ W1^T + x[self[i],:] @ W2^T
// Virtual K=256 (chunk0: agg/W1, chunk1: x[self]/W2), bf16 hi/lo split,
// D += Ah·Bh + Ah·Bl + Al·Bh with fp32 register accumulators.
// Block: 64x128 out, 256 threads (8 warps in 2x4), warp tile 32x32,
// per-warp frags: 2 m-frags (m16) x 4 n-frags (n8), k-steps of 16.
// Smem ~105 KB -> 2 CTAs/SM; co-resident CTA's MMAs hide load/epilogue gaps.
// ===========================================================================
#define TILE_M    64
#define ASTRIDE   136      // bf16 elems per smem row (128 + 8 pad); 272B rows
#define A_SM_BYTES (TILE_M * ASTRIDE * 2)    // 17408
#define B_SM_BYTES (128 * ASTRIDE * 2)       // 34816
#define SMEM_SINV 0                          // float[64]
#define SMEM_SELF 256                        // int[64]
#define SMEM_AHI  512
#define SMEM_ALO  (SMEM_AHI + A_SM_BYTES)    // 17920
#define SMEM_BHI  (SMEM_ALO + A_SM_BYTES)    // 35328
#define SMEM_BLO  (SMEM_BHI + B_SM_BYTES)    // 70144
#define SMEM_BYTES (SMEM_BLO + B_SM_BYTES)   // 104,960 B

#define GEMM_THREADS 256

__global__ __launch_bounds__(GEMM_THREADS, 2)
void sage_mma_gemm_kernel(const float* __restrict__ x,
                          const float* __restrict__ degree,
                          const int* __restrict__ self_ids,
                          float* __restrict__ out) {
    extern __shared__ char smem[];
    uint32_t sb = smem_to_u32(smem);
    const int tid  = threadIdx.x;
    const int wid  = tid >> 5;
    const int lane = tid & 31;
    const int row0 = blockIdx.x * TILE_M;

    const int warp_m = wid & 1;    // 0..1 -> 32-row block
    const int warp_n = wid >> 1;   // 0..3 -> 32-col block

    float* sinv  = (float*)(smem + SMEM_SINV);
    int*   sself = (int*)(smem + SMEM_SELF);

    if (tid < TILE_M) {
        int r  = row0 + tid;
        int rc = (r < N_DSTN) ? r : (N_DSTN - 1);
        sinv[tid]  = 1.0f / degree[rc];
        sself[tid] = self_ids[rc];
    }

    // accumulators: [m-frag][n-frag][4]
    float acc[2][4][4];
#pragma unroll
    for (int mf = 0; mf < 2; ++mf)
#pragma unroll
        for (int nf = 0; nf < 4; ++nf)
#pragma unroll
            for (int q = 0; q < 4; ++q) acc[mf][nf][q] = 0.0f;

    __syncthreads();   // sinv/sself visible

    // precomputed ldmatrix lane address components
    const int a_row  = warp_m * 32 + (lane & 15);       // + mf*16
    const int a_koff = (lane >> 4) * 8;                 // + k0
    const int b_row  = warp_n * 32 + (lane & 7);        // + nf*8
    const int b_koff = ((lane >> 3) & 1) * 8;           // + k0

#pragma unroll
    for (int chunk = 0; chunk < 2; ++chunk) {
        // ---- A tile: gather fp32, scale, split into padded row-major bf16 ----
#pragma unroll
        for (int it = 0; it < 8; ++it) {
            int idx = it * GEMM_THREADS + tid;     // 0..2047
            int k4  = idx & 31;
            int i   = idx >> 5;                    // 0..63
            float4 v;
            if (chunk == 0) {
                int r  = row0 + i;
                int rc = (r < N_DSTN) ? r : (N_DSTN - 1);
                v = *((const float4*)(out + (size_t)rc * DFEAT) + k4);
                float s = sinv[i];
                v.x *= s; v.y *= s; v.z *= s; v.w *= s;
            } else {
                v = *((const float4*)(x + (size_t)sself[i] * DFEAT) + k4);
            }
            uint32_t off = (uint32_t)(i * ASTRIDE + k4 * 4) * 2;
            split_store4(smem + SMEM_AHI, smem + SMEM_ALO, off, v);
        }
        // ---- B tiles: copy pre-split weights into padded smem rows ----
        {
            const uint4* ghi = (const uint4*)g_wtiles[chunk * 2 + 0];
            const uint4* glo = (const uint4*)g_wtiles[chunk * 2 + 1];
#pragma unroll
            for (int it = 0; it < 8; ++it) {
                int idx = it * GEMM_THREADS + tid;   // 0..2047
                int j   = idx >> 4;                  // row (16 x 16B per row)
                int kq  = idx & 15;
                uint32_t off = (uint32_t)(j * ASTRIDE) * 2 + (uint32_t)kq * 16;
                *(uint4*)(smem + SMEM_BHI + off) = __ldg(ghi + idx);
                *(uint4*)(smem + SMEM_BLO + off) = __ldg(glo + idx);
            }
        }
        __syncthreads();

        // ---- compute: 8 k-steps of 16; 3 products per (mf, nf) ----
#pragma unroll
        for (int ks = 0; ks < 8; ++ks) {
            const int k0 = ks * 16;
            uint32_t ah[2][4], al[2][4], bh[4][2], bl[4][2];
#pragma unroll
            for (int mf = 0; mf < 2; ++mf) {
                uint32_t boff = (uint32_t)((a_row + mf * 16) * ASTRIDE + k0 + a_koff) * 2;
                ldmatrix_x4(ah[mf], sb + SMEM_AHI + boff);
                ldmatrix_x4(al[mf], sb + SMEM_ALO + boff);
            }
#pragma unroll
            for (int nf = 0; nf < 4; ++nf) {
                uint32_t boff = (uint32_t)((b_row + nf * 8) * ASTRIDE + k0 + b_koff) * 2;
                ldmatrix_x2(bh[nf], sb + SMEM_BHI + boff);
                ldmatrix_x2(bl[nf], sb + SMEM_BLO + boff);
            }
#pragma unroll
            for (int mf = 0; mf < 2; ++mf)
#pragma unroll
                for (int nf = 0; nf < 4; ++nf) {
                    mma_16816(acc[mf][nf], ah[mf], bh[nf]);
                    mma_16816(acc[mf][nf], ah[mf], bl[nf]);
                    mma_16816(acc[mf][nf], al[mf], bh[nf]);
                }
        }
        __syncthreads();   // done reading smem before next chunk overwrites
    }

    // ---- epilogue: direct stores (float2 per frag row; 32B per quad) ----
#pragma unroll
    for (int mf = 0; mf < 2; ++mf) {
#pragma unroll
        for (int nf = 0; nf < 4; ++nf) {
            int r0 = row0 + warp_m * 32 + mf * 16 + (lane >> 2);
            int r1 = r0 + 8;
            int col = warp_n * 32 + nf * 8 + (lane & 3) * 2;
            if (r0 < N_DSTN)
                *(float2*)(out + (size_t)r0 * DFEAT + col) =
                    make_float2(acc[mf][nf][0], acc[mf][nf][1]);
            if (r1 < N_DSTN)
                *(float2*)(out + (size_t)r1 * DFEAT + col) =
                    make_float2(acc[mf][nf][2], acc[mf][nf][3]);
        }
    }
}

// ===========================================================================
// Launch: prep_weights + memset(out) -> scatter -> mma GEMM (in place).
// All stream-ordered, graph-capturable, allocation-free.
// ===========================================================================
extern "C" void kernel_launch(void* const* d_in, const int* in_sizes, int n_in,
                              void* d_out, int out_size) {
    const float* x        = (const float*)d_in[0];
    const float* W1       = (const float*)d_in[1];
    const float* W2       = (const float*)d_in[2];
    const float* degree   = (const float*)d_in[3];
    const int*   src_idx  = (const int*)d_in[4];
    const int*   dst_idx  = (const int*)d_in[5];
    const int*   self_ids = (const int*)d_in[6];
    float*       out      = (float*)d_out;

    (void)in_sizes; (void)n_in; (void)out_size;

    prep_weights_kernel<<<32, 256>>>(W1, W2);
    cudaMemsetAsync(out, 0, (size_t)N_DSTN * DFEAT * sizeof(float));

    sage_scatter_kernel<<<N_EDGE / 8, 256>>>(x, src_idx, dst_idx, out);

    cudaFuncSetAttribute(sage_mma_gemm_kernel,
                         cudaFuncAttributeMaxDynamicSharedMemorySize, SMEM_BYTES);
    int gemm_blocks = (N_DSTN + TILE_M - 1) / TILE_M;   // 1563
    sage_mma_gemm_kernel<<<gemm_blocks, GEMM_THREADS, SMEM_BYTES>>>(
        x, degree, self_ids, out);
}